// round 14
// baseline (speedup 1.0000x reference)
#include <cuda_runtime.h>
#include <cuda_fp16.h>
#include <cstdint>
#include <math.h>

// Problem constants
#define BB 4
#define CC 256
#define HH 252
#define WW 252
#define HP 256
#define WP 256

// Q/K/V and attention-output slabs, fp16, layout [wh=32768][d=32][pix=64]
__device__ __half g_Q[67108864];
__device__ __half g_K[67108864];
__device__ __half g_V[67108864];
__device__ __half g_O[67108864];
// fp16 weights: wq(256x256) | wkv(512x256) | wproj(256x256)
__device__ __half g_W[262144];

// ---------------------------------------------------------------------------
__device__ __forceinline__ uint32_t smem_u32(const void* p) {
    uint32_t a;
    asm("{ .reg .u64 t; cvta.to.shared.u64 t, %1; cvt.u32.u64 %0, t; }"
        : "=r"(a) : "l"(p));
    return a;
}
#define LDSM_X4(r0, r1, r2, r3, addr)                                          \
    asm volatile("ldmatrix.sync.aligned.m8n8.x4.shared.b16 {%0,%1,%2,%3}, [%4];" \
                 : "=r"(r0), "=r"(r1), "=r"(r2), "=r"(r3) : "r"(addr))
#define LDSM_X4_T(r0, r1, r2, r3, addr)                                        \
    asm volatile("ldmatrix.sync.aligned.m8n8.x4.trans.shared.b16 {%0,%1,%2,%3}, [%4];" \
                 : "=r"(r0), "=r"(r1), "=r"(r2), "=r"(r3) : "r"(addr))
__device__ __forceinline__ void mma_f16(float* d, const uint32_t* a,
                                        uint32_t b0, uint32_t b1) {
    asm volatile(
        "mma.sync.aligned.m16n8k16.row.col.f32.f16.f16.f32 "
        "{%0,%1,%2,%3}, {%4,%5,%6,%7}, {%8,%9}, {%0,%1,%2,%3};"
        : "+f"(d[0]), "+f"(d[1]), "+f"(d[2]), "+f"(d[3])
        : "r"(a[0]), "r"(a[1]), "r"(a[2]), "r"(a[3]), "r"(b0), "r"(b1));
}
__device__ __forceinline__ uint32_t pack_half(float a, float b) {
    __half2 v;
    v.x = __float2half_rn(a);
    v.y = __float2half_rn(b);
    return *reinterpret_cast<uint32_t*>(&v);
}
__device__ __forceinline__ void cpa16(uint32_t dst, const void* src) {
    asm volatile("cp.async.cg.shared.global [%0], [%1], 16;" :: "r"(dst), "l"(src));
}
#define CP_COMMIT() asm volatile("cp.async.commit_group;" ::: "memory")
#define CP_WAIT(n)  asm volatile("cp.async.wait_group %0;" :: "n"(n) : "memory")

// ---------------------------------------------------------------------------
__global__ void prep_w(const float* __restrict__ wq, const float* __restrict__ wkv,
                       const float* __restrict__ wproj)
{
    int i = blockIdx.x * 256 + threadIdx.x;
    float v;
    if (i < 65536)       v = wq[i];
    else if (i < 196608) v = wkv[i - 65536];
    else                 v = wproj[i - 196608];
    g_W[i] = __float2half_rn(v);
}

// ---------------------------------------------------------------------------
// proj_v7: B-resident + warp-private A staging, barrier-free mainloop.
// MODE 0/1: fp32->fp16 conversion fused into B staging from original inputs.
// MODE 2:   B staged from the O slab (window layout) via contiguous 16B lines.
// MODE 0 -> g_Q (NOC=2), 1 -> g_K/g_V (NOC=4), 2 -> Out+bias (NOC=2).
// ---------------------------------------------------------------------------
#define PB_PITCH 272
#define PB_BYTES (256 * PB_PITCH)            // 69632
#define PA_OFF   PB_BYTES
#define PA_WSTG  2560                        // 32 rows * 80B (pitch-padded)
#define PA_WARP  (2 * PA_WSTG)               // 2 stages per warp
#define P_SMEM   (PA_OFF + 8 * PA_WARP)      // 110592

__device__ __forceinline__ void issue_Aw(
    uint32_t wbuf, int lane, int woff, int warp_m, int jchunk)
{
    const int oc0 = (jchunk >> 3) * 128;
    const int k0  = (jchunk & 7) * 32;
    const uint32_t st = wbuf + (uint32_t)(jchunk & 1) * PA_WSTG;
    #pragma unroll
    for (int it = 0; it < 4; it++) {
        const int idx = it * 32 + lane;      // 0..127 (16B units)
        const int row = idx >> 2;            // 0..31
        const int j   = idx & 3;             // 0..3 (8 halves each)
        cpa16(st + (uint32_t)(row * 80 + j * 16),
              g_W + woff + (oc0 + warp_m * 32 + row) * 256 + k0 + j * 8);
    }
}

template <int MODE>
__global__ __launch_bounds__(256, 2)
void proj_v7(const void* __restrict__ Bsrc, int woff,
             const float* __restrict__ bias, float* __restrict__ Out)
{
    constexpr int NOC = (MODE == 1) ? 4 : 2;
    extern __shared__ char smem[];
    const uint32_t sb = smem_u32(smem);

    const int tid  = threadIdx.x;
    const int wid  = tid >> 5;
    const int lane = tid & 31;
    const int warp_m = wid & 3;
    const int warp_n = wid >> 2;

    const int p0  = blockIdx.x * 128;
    const int b   = p0 >> 16;
    const int rem = p0 & 65535;
    const int h   = rem >> 8;
    const int w0  = rem & 255;

    const uint32_t wbuf = sb + PA_OFF + (uint32_t)(wid * PA_WARP);

    // ---- prologue: stage full B column [256ch][128px] ----
    if (MODE == 2) {
        // gather from O slab: 8 consecutive w in a window = 8 consecutive l
        const __half* Os = (const __half*)Bsrc;
        const int nwbase = (b * 32 + (h >> 3)) * 32 + (w0 >> 3);
        const int lb = (h & 7) * 8;
        #pragma unroll
        for (int it = 0; it < 16; it++) {
            const int idx = it * 256 + tid;      // 0..4095, 16B each
            const int c  = idx >> 4;
            const int jw = idx & 15;             // window within row tile
            cpa16(sb + (uint32_t)(c * PB_PITCH + jw * 16),
                  Os + ((((nwbase + jw) * 8 + (c >> 5)) * 32 + (c & 31)) * 64 + lb));
        }
        CP_COMMIT();
    } else {
        // direct fp32 source + inline conversion (252 % 4 == 0: each float4
        // is fully valid or fully padding — no partial vectors)
        const float* Xf = (const float*)Bsrc;
        #pragma unroll 8
        for (int it = 0; it < 32; it++) {
            const int idx = it * 256 + tid;      // 0..8191 (float4 units)
            const int c = idx >> 5;              // channel 0..255
            const int q = idx & 31;              // float4 index (px = 4q)
            float4 v = make_float4(0.f, 0.f, 0.f, 0.f);
            if (h < HH && (w0 + q * 4) < WW)
                v = *reinterpret_cast<const float4*>(
                    &Xf[((size_t)(b * 256 + c) * HH + h) * WW + w0 + q * 4]);
            uint2 p;
            p.x = pack_half(v.x, v.y);
            p.y = pack_half(v.z, v.w);
            *reinterpret_cast<uint2*>(smem + c * PB_PITCH + q * 8) = p;
        }
    }
    issue_Aw(wbuf, lane, woff, warp_m, 0); CP_COMMIT();
    issue_Aw(wbuf, lane, woff, warp_m, 1); CP_COMMIT();
    if (MODE == 2) CP_WAIT(2);   // B group done; A0/A1 pending
    __syncthreads();             // the ONLY CTA barrier
    int jnext = 2;

    const uint32_t bLaneOff = (uint32_t)(((lane & 7) + ((lane >> 3) & 1) * 8) * PB_PITCH
                                         + (warp_n * 64 + (lane >> 4) * 8) * 2);
    const uint32_t aLaneOff = (uint32_t)((lane & 15) * 80 + (lane >> 4) * 16);

    for (int ob = 0; ob < NOC; ob++) {
        float acc[2][8][4];
        #pragma unroll
        for (int i = 0; i < 2; i++)
            #pragma unroll
            for (int j = 0; j < 8; j++)
                #pragma unroll
                for (int k = 0; k < 4; k++) acc[i][j][k] = 0.f;

        for (int ch = 0; ch < 8; ch++) {
            const int jcur = ob * 8 + ch;
            CP_WAIT(1);
            __syncwarp();

            const uint32_t uA = wbuf + (uint32_t)(jcur & 1) * PA_WSTG;

            #pragma unroll
            for (int s = 0; s < 2; s++) {
                uint32_t bh[4][4];
                #pragma unroll
                for (int np = 0; np < 4; np++) {
                    const uint32_t bo = bLaneOff
                        + (uint32_t)((ch * 32 + s * 16) * PB_PITCH + np * 32);
                    LDSM_X4_T(bh[np][0], bh[np][1], bh[np][2], bh[np][3], sb + bo);
                }
                #pragma unroll
                for (int mt = 0; mt < 2; mt++) {
                    uint32_t ah[4];
                    const uint32_t ao = aLaneOff + (uint32_t)(mt * 16 * 80 + s * 32);
                    LDSM_X4(ah[0], ah[1], ah[2], ah[3], uA + ao);
                    #pragma unroll
                    for (int np = 0; np < 4; np++)
                        #pragma unroll
                        for (int half = 0; half < 2; half++)
                            mma_f16(acc[mt][np * 2 + half], ah,
                                    bh[np][half * 2], bh[np][half * 2 + 1]);
                }
            }
            if (jnext < NOC * 8) {
                issue_Aw(wbuf, lane, woff, warp_m, jnext);
                jnext++;
            }
            CP_COMMIT();   // unconditional: empty tail groups keep wait(1) safe
        }

        // ---- epilogue for this oc block ----
        const int oc0 = ob * 128;
        #pragma unroll
        for (int mt = 0; mt < 2; mt++) {
            const int mBase = warp_m * 32 + mt * 16 + (lane >> 2);
            #pragma unroll
            for (int oct = 0; oct < 8; oct++) {
                const int n = warp_n * 64 + oct * 8 + 2 * (lane & 3);
                const float* d = acc[mt][oct];
                #pragma unroll
                for (int rr = 0; rr < 2; rr++) {
                    const int oc = oc0 + mBase + rr * 8;
                    float v0 = d[rr * 2 + 0];
                    float v1 = d[rr * 2 + 1];
                    if (MODE == 2) {
                        const float bs = bias[oc];
                        const int w = w0 + n;
                        if (h < HH) {
                            if (w < WW)
                                Out[((size_t)(b * 256 + oc) * HH + h) * WW + w] = v0 + bs;
                            if (w + 1 < WW)
                                Out[((size_t)(b * 256 + oc) * HH + h) * WW + w + 1] = v1 + bs;
                        }
                    } else {
                        if (MODE == 0) {
                            v0 *= 0.1767766952966369f;   // fold softmax scale into Q
                            v1 *= 0.1767766952966369f;
                        }
                        const int w  = w0 + n;
                        const int nw = (b * 32 + (h >> 3)) * 32 + (w >> 3);
                        const int l  = ((h & 7) << 3) | (w & 7);
                        const int cc = oc & 255;
                        const int idx2 = (((nw * 8 + (cc >> 5)) * 32 + (cc & 31)) * 64 + l) >> 1;
                        uint32_t* dst;
                        if (MODE == 0)     dst = reinterpret_cast<uint32_t*>(g_Q);
                        else if (ob < 2)   dst = reinterpret_cast<uint32_t*>(g_K);
                        else               dst = reinterpret_cast<uint32_t*>(g_V);
                        dst[idx2] = pack_half(v0, v1);
                    }
                }
            }
        }
    }
}

// ---------------------------------------------------------------------------
// fp16 MMA attention: block = 128 threads = 2 window-heads, 2 warps per wh.
// Output written as O slab [wh][d][l] via smem transpose + coalesced STG.
// ---------------------------------------------------------------------------
#define SLAB 4608                 // 32 rows * 144B
#define WHSZ (3 * SLAB)           // Q K V
#define O_OFF (2 * WHSZ)          // 27648
#define O_PITCH 144
#define O_WH (32 * O_PITCH)       // 4608
#define ATT_SMEM (O_OFF + 2 * O_WH)   // 36864

__global__ __launch_bounds__(128)
void attn_mma()
{
    extern __shared__ char smem[];
    const int tid  = threadIdx.x;
    const int wid  = tid >> 5;
    const int lane = tid & 31;

    const __half* srcs[3] = {g_Q, g_K, g_V};
    #pragma unroll
    for (int sl = 0; sl < 2; sl++) {
        const size_t gbase = (size_t)(blockIdx.x * 2 + sl) * 2048;
        #pragma unroll
        for (int a = 0; a < 3; a++) {
            const uint4* src = reinterpret_cast<const uint4*>(srcs[a] + gbase);
            char* dstb = smem + sl * WHSZ + a * SLAB;
            #pragma unroll
            for (int i = 0; i < 2; i++) {
                const int idx = i * 128 + tid;
                const uint4 v = src[idx];
                *reinterpret_cast<uint4*>(dstb + (idx >> 3) * 144 + (idx & 7) * 16) = v;
            }
        }
    }
    __syncthreads();

    const uint32_t sb = smem_u32(smem) + (wid >> 1) * WHSZ;
    const uint32_t uQ = sb, uK = sb + SLAB, uV = sb + 2 * SLAB;
    const int whalf = wid & 1;

    const int g = lane >> 2;
    const int t = lane & 3;

    char* obase = smem + O_OFF + (wid >> 1) * O_WH;

    const uint32_t qRow = (uint32_t)((lane & 7) + ((lane >> 4) & 1) * 8);
    const uint32_t qCol = (uint32_t)(((lane >> 3) & 1) * 16);
    const uint32_t kRow = (uint32_t)((lane & 7) + ((lane >> 3) & 1) * 8);
    const uint32_t kCol = (uint32_t)((lane >> 4) * 16);
    const uint32_t vRow = (uint32_t)((lane & 7) + ((lane >> 4) & 1) * 8);
    const uint32_t vCol = (uint32_t)(((lane >> 3) & 1) * 16);

    #pragma unroll
    for (int mt = 0; mt < 2; mt++) {
        const int ltile = whalf * 2 + mt;

        float s[8][4];
        #pragma unroll
        for (int j = 0; j < 8; j++)
            #pragma unroll
            for (int k = 0; k < 4; k++) s[j][k] = 0.f;

        #pragma unroll
        for (int kt = 0; kt < 2; kt++) {
            uint32_t ah[4];
            const uint32_t ao = (qRow + kt * 16) * 144 + qCol + (uint32_t)(ltile * 32);
            LDSM_X4_T(ah[0], ah[1], ah[2], ah[3], uQ + ao);
            #pragma unroll
            for (int nt = 0; nt < 4; nt++) {
                uint32_t bh[4];
                const uint32_t bo = (kRow + kt * 16) * 144 + kCol + (uint32_t)(nt * 32);
                LDSM_X4_T(bh[0], bh[1], bh[2], bh[3], uK + bo);
                #pragma unroll
                for (int half = 0; half < 2; half++)
                    mma_f16(s[nt * 2 + half], ah, bh[half * 2], bh[half * 2 + 1]);
            }
        }

        float mx0 = -1e30f, mx1 = -1e30f;
        #pragma unroll
        for (int j = 0; j < 8; j++) {
            mx0 = fmaxf(mx0, fmaxf(s[j][0], s[j][1]));
            mx1 = fmaxf(mx1, fmaxf(s[j][2], s[j][3]));
        }
        mx0 = fmaxf(mx0, __shfl_xor_sync(0xffffffffu, mx0, 1));
        mx0 = fmaxf(mx0, __shfl_xor_sync(0xffffffffu, mx0, 2));
        mx1 = fmaxf(mx1, __shfl_xor_sync(0xffffffffu, mx1, 1));
        mx1 = fmaxf(mx1, __shfl_xor_sync(0xffffffffu, mx1, 2));

        float sum0 = 0.f, sum1 = 0.f;
        uint32_t ph01[8], ph23[8];
        #pragma unroll
        for (int j = 0; j < 8; j++) {
            const float e0 = __expf(s[j][0] - mx0);
            const float e1 = __expf(s[j][1] - mx0);
            const float e2 = __expf(s[j][2] - mx1);
            const float e3 = __expf(s[j][3] - mx1);
            sum0 += e0 + e1;
            sum1 += e2 + e3;
            ph01[j] = pack_half(e0, e1);
            ph23[j] = pack_half(e2, e3);
        }
        sum0 += __shfl_xor_sync(0xffffffffu, sum0, 1);
        sum0 += __shfl_xor_sync(0xffffffffu, sum0, 2);
        sum1 += __shfl_xor_sync(0xffffffffu, sum1, 1);
        sum1 += __shfl_xor_sync(0xffffffffu, sum1, 2);
        const float inv0 = 1.f / sum0;
        const float inv1 = 1.f / sum1;

        float o[4][4];
        #pragma unroll
        for (int j = 0; j < 4; j++)
            #pragma unroll
            for (int k = 0; k < 4; k++) o[j][k] = 0.f;

        #pragma unroll
        for (int kt = 0; kt < 4; kt++) {
            uint32_t ap[4];
            ap[0] = ph01[2 * kt];     ap[1] = ph23[2 * kt];
            ap[2] = ph01[2 * kt + 1]; ap[3] = ph23[2 * kt + 1];
            #pragma unroll
            for (int dt2 = 0; dt2 < 2; dt2++) {
                uint32_t bh[4];
                const uint32_t bo = (vRow + dt2 * 16) * 144 + vCol + (uint32_t)(kt * 32);
                LDSM_X4(bh[0], bh[1], bh[2], bh[3], uV + bo);
                #pragma unroll
                for (int half = 0; half < 2; half++)
                    mma_f16(o[dt2 * 2 + half], ap, bh[half * 2], bh[half * 2 + 1]);
            }
        }

        // ---- store O frags to smem [d][l] (pitch 144) ----
        const int l0 = ltile * 16 + g;
        const int l1 = l0 + 8;
        #pragma unroll
        for (int dt = 0; dt < 4; dt++) {
            const int d0 = dt * 8 + 2 * t;
            *(__half*)(obase + d0 * O_PITCH + l0 * 2)
                = __float2half_rn(o[dt][0] * inv0);
            *(__half*)(obase + (d0 + 1) * O_PITCH + l0 * 2)
                = __float2half_rn(o[dt][1] * inv0);
            *(__half*)(obase + d0 * O_PITCH + l1 * 2)
                = __float2half_rn(o[dt][2] * inv1);
            *(__half*)(obase + (d0 + 1) * O_PITCH + l1 * 2)
                = __float2half_rn(o[dt][3] * inv1);
        }
    }

    // ---- coalesced slab write: 2 wh x 2048 halves ----
    __syncthreads();
    const size_t og = (size_t)blockIdx.x * 4096;
    #pragma unroll
    for (int i = 0; i < 4; i++) {
        const int u = i * 128 + tid;          // 0..511 uint4
        const int whs = u >> 8;
        const int rm  = u & 255;
        const int d = rm >> 3, j = rm & 7;
        const uint4 v = *reinterpret_cast<const uint4*>(
            smem + O_OFF + whs * O_WH + d * O_PITCH + j * 16);
        *reinterpret_cast<uint4*>(g_O + og + whs * 2048 + d * 64 + j * 8) = v;
    }
}

// ---------------------------------------------------------------------------
extern "C" void kernel_launch(void* const* d_in, const int* in_sizes, int n_in,
                              void* d_out, int out_size)
{
    const float* x_q    = (const float*)d_in[0];
    const float* x_kv   = (const float*)d_in[1];
    const float* w_q    = (const float*)d_in[2];
    const float* w_kv   = (const float*)d_in[3];
    const float* w_proj = (const float*)d_in[4];
    const float* b_proj = (const float*)d_in[5];
    float* out = (float*)d_out;

    cudaFuncSetAttribute(attn_mma, cudaFuncAttributeMaxDynamicSharedMemorySize, ATT_SMEM);
    cudaFuncSetAttribute(proj_v7<0>, cudaFuncAttributeMaxDynamicSharedMemorySize, P_SMEM);
    cudaFuncSetAttribute(proj_v7<1>, cudaFuncAttributeMaxDynamicSharedMemorySize, P_SMEM);
    cudaFuncSetAttribute(proj_v7<2>, cudaFuncAttributeMaxDynamicSharedMemorySize, P_SMEM);

    __half* oi;
    cudaGetSymbolAddress((void**)&oi, g_O);

    prep_w<<<1024, 256>>>(w_q, w_kv, w_proj);

    const int pixTiles = (BB * HP * WP) / 128;   // 2048
    proj_v7<0><<<pixTiles, 256, P_SMEM>>>(x_q,  0,      nullptr, nullptr);
    proj_v7<1><<<pixTiles, 256, P_SMEM>>>(x_kv, 65536,  nullptr, nullptr);
    attn_mma<<<16384, 128, ATT_SMEM>>>();
    proj_v7<2><<<pixTiles, 256, P_SMEM>>>(oi, 196608, b_proj, out);
}

// round 15
// speedup vs baseline: 1.0295x; 1.0295x over previous
#include <cuda_runtime.h>
#include <cuda_fp16.h>
#include <cstdint>
#include <math.h>

// Problem constants
#define BB 4
#define CC 256
#define HH 252
#define WW 252
#define HP 256
#define WP 256

// Q/K/V and attention-output slabs, fp16, layout [wh=32768][d=32][pix=64]
__device__ __half g_Q[67108864];
__device__ __half g_K[67108864];
__device__ __half g_V[67108864];
__device__ __half g_O[67108864];
// fp16 weights: wq(256x256) | wkv(512x256) | wproj(256x256)
__device__ __half g_W[262144];

// ---------------------------------------------------------------------------
__device__ __forceinline__ uint32_t smem_u32(const void* p) {
    uint32_t a;
    asm("{ .reg .u64 t; cvta.to.shared.u64 t, %1; cvt.u32.u64 %0, t; }"
        : "=r"(a) : "l"(p));
    return a;
}
#define LDSM_X4(r0, r1, r2, r3, addr)                                          \
    asm volatile("ldmatrix.sync.aligned.m8n8.x4.shared.b16 {%0,%1,%2,%3}, [%4];" \
                 : "=r"(r0), "=r"(r1), "=r"(r2), "=r"(r3) : "r"(addr))
#define LDSM_X4_T(r0, r1, r2, r3, addr)                                        \
    asm volatile("ldmatrix.sync.aligned.m8n8.x4.trans.shared.b16 {%0,%1,%2,%3}, [%4];" \
                 : "=r"(r0), "=r"(r1), "=r"(r2), "=r"(r3) : "r"(addr))
__device__ __forceinline__ void mma_f16(float* d, const uint32_t* a,
                                        uint32_t b0, uint32_t b1) {
    asm volatile(
        "mma.sync.aligned.m16n8k16.row.col.f32.f16.f16.f32 "
        "{%0,%1,%2,%3}, {%4,%5,%6,%7}, {%8,%9}, {%0,%1,%2,%3};"
        : "+f"(d[0]), "+f"(d[1]), "+f"(d[2]), "+f"(d[3])
        : "r"(a[0]), "r"(a[1]), "r"(a[2]), "r"(a[3]), "r"(b0), "r"(b1));
}
__device__ __forceinline__ uint32_t pack_half(float a, float b) {
    __half2 v;
    v.x = __float2half_rn(a);
    v.y = __float2half_rn(b);
    return *reinterpret_cast<uint32_t*>(&v);
}
__device__ __forceinline__ void cpa16(uint32_t dst, const void* src) {
    asm volatile("cp.async.cg.shared.global [%0], [%1], 16;" :: "r"(dst), "l"(src));
}
#define CP_COMMIT() asm volatile("cp.async.commit_group;" ::: "memory")
#define CP_WAIT(n)  asm volatile("cp.async.wait_group %0;" :: "n"(n) : "memory")

// ---------------------------------------------------------------------------
__global__ void prep_w(const float* __restrict__ wq, const float* __restrict__ wkv,
                       const float* __restrict__ wproj)
{
    int i = blockIdx.x * 256 + threadIdx.x;
    float v;
    if (i < 65536)       v = wq[i];
    else if (i < 196608) v = wkv[i - 65536];
    else                 v = wproj[i - 196608];
    g_W[i] = __float2half_rn(v);
}

// ---------------------------------------------------------------------------
// proj_v8: B-resident + warp-private A staging, barrier-free mainloop.
// MODE 0/1: pixel tile = 128 consecutive w at fixed (b,h); fp32->fp16
//           conversion fused into B staging from original inputs.
// MODE 2:   pixel tile = TWO whole windows (2 x 64 l); B staged from the O
//           slab via fully contiguous 128B rows per channel.
// MODE 0 -> g_Q (NOC=2), 1 -> g_K/g_V (NOC=4), 2 -> Out+bias (NOC=2).
// ---------------------------------------------------------------------------
#define PB_PITCH 272
#define PB_BYTES (256 * PB_PITCH)            // 69632
#define PA_OFF   PB_BYTES
#define PA_WSTG  2560                        // 32 rows * 80B (pitch-padded)
#define PA_WARP  (2 * PA_WSTG)               // 2 stages per warp
#define P_SMEM   (PA_OFF + 8 * PA_WARP)      // 110592

__device__ __forceinline__ void issue_Aw(
    uint32_t wbuf, int lane, int woff, int warp_m, int jchunk)
{
    const int oc0 = (jchunk >> 3) * 128;
    const int k0  = (jchunk & 7) * 32;
    const uint32_t st = wbuf + (uint32_t)(jchunk & 1) * PA_WSTG;
    #pragma unroll
    for (int it = 0; it < 4; it++) {
        const int idx = it * 32 + lane;      // 0..127 (16B units)
        const int row = idx >> 2;            // 0..31
        const int j   = idx & 3;             // 0..3 (8 halves each)
        cpa16(st + (uint32_t)(row * 80 + j * 16),
              g_W + woff + (oc0 + warp_m * 32 + row) * 256 + k0 + j * 8);
    }
}

template <int MODE>
__global__ __launch_bounds__(256, 2)
void proj_v8(const void* __restrict__ Bsrc, int woff,
             const float* __restrict__ bias, float* __restrict__ Out)
{
    constexpr int NOC = (MODE == 1) ? 4 : 2;
    extern __shared__ char smem[];
    const uint32_t sb = smem_u32(smem);

    const int tid  = threadIdx.x;
    const int wid  = tid >> 5;
    const int lane = tid & 31;
    const int warp_m = wid & 3;
    const int warp_n = wid >> 2;

    // MODE 0/1 tile geometry (image rows)
    const int p0  = blockIdx.x * 128;
    const int b   = p0 >> 16;
    const int rem = p0 & 65535;
    const int h   = rem >> 8;
    const int w0  = rem & 255;
    // MODE 2 tile geometry (two windows)
    const int nw0 = blockIdx.x * 2;

    const uint32_t wbuf = sb + PA_OFF + (uint32_t)(wid * PA_WARP);

    // ---- prologue: stage full B column [256ch][128px] ----
    if (MODE == 2) {
        // two whole windows: per channel, 2 x 128B contiguous slab rows
        const __half* Os = (const __half*)Bsrc;
        #pragma unroll
        for (int it = 0; it < 16; it++) {
            const int idx = it * 256 + tid;      // 0..4095, 16B each
            const int c  = idx >> 4;
            const int jw = (idx >> 3) & 1;       // which window
            const int j  = idx & 7;              // 16B line within the row
            cpa16(sb + (uint32_t)(c * PB_PITCH + jw * 128 + j * 16),
                  Os + ((((nw0 + jw) * 8 + (c >> 5)) * 32 + (c & 31)) * 64 + j * 8));
        }
        CP_COMMIT();
    } else {
        // direct fp32 source + inline conversion (252 % 4 == 0: each float4
        // is fully valid or fully padding — no partial vectors)
        const float* Xf = (const float*)Bsrc;
        #pragma unroll 8
        for (int it = 0; it < 32; it++) {
            const int idx = it * 256 + tid;      // 0..8191 (float4 units)
            const int c = idx >> 5;              // channel 0..255
            const int q = idx & 31;              // float4 index (px = 4q)
            float4 v = make_float4(0.f, 0.f, 0.f, 0.f);
            if (h < HH && (w0 + q * 4) < WW)
                v = *reinterpret_cast<const float4*>(
                    &Xf[((size_t)(b * 256 + c) * HH + h) * WW + w0 + q * 4]);
            uint2 p;
            p.x = pack_half(v.x, v.y);
            p.y = pack_half(v.z, v.w);
            *reinterpret_cast<uint2*>(smem + c * PB_PITCH + q * 8) = p;
        }
    }
    issue_Aw(wbuf, lane, woff, warp_m, 0); CP_COMMIT();
    issue_Aw(wbuf, lane, woff, warp_m, 1); CP_COMMIT();
    if (MODE == 2) CP_WAIT(2);   // B group done; A0/A1 pending
    __syncthreads();             // the ONLY CTA barrier
    int jnext = 2;

    const uint32_t bLaneOff = (uint32_t)(((lane & 7) + ((lane >> 3) & 1) * 8) * PB_PITCH
                                         + (warp_n * 64 + (lane >> 4) * 8) * 2);
    const uint32_t aLaneOff = (uint32_t)((lane & 15) * 80 + (lane >> 4) * 16);

    for (int ob = 0; ob < NOC; ob++) {
        float acc[2][8][4];
        #pragma unroll
        for (int i = 0; i < 2; i++)
            #pragma unroll
            for (int j = 0; j < 8; j++)
                #pragma unroll
                for (int k = 0; k < 4; k++) acc[i][j][k] = 0.f;

        for (int ch = 0; ch < 8; ch++) {
            const int jcur = ob * 8 + ch;
            CP_WAIT(1);
            __syncwarp();

            const uint32_t uA = wbuf + (uint32_t)(jcur & 1) * PA_WSTG;

            #pragma unroll
            for (int s = 0; s < 2; s++) {
                uint32_t bh[4][4];
                #pragma unroll
                for (int np = 0; np < 4; np++) {
                    const uint32_t bo = bLaneOff
                        + (uint32_t)((ch * 32 + s * 16) * PB_PITCH + np * 32);
                    LDSM_X4_T(bh[np][0], bh[np][1], bh[np][2], bh[np][3], sb + bo);
                }
                #pragma unroll
                for (int mt = 0; mt < 2; mt++) {
                    uint32_t ah[4];
                    const uint32_t ao = aLaneOff + (uint32_t)(mt * 16 * 80 + s * 32);
                    LDSM_X4(ah[0], ah[1], ah[2], ah[3], uA + ao);
                    #pragma unroll
                    for (int np = 0; np < 4; np++)
                        #pragma unroll
                        for (int half = 0; half < 2; half++)
                            mma_f16(acc[mt][np * 2 + half], ah,
                                    bh[np][half * 2], bh[np][half * 2 + 1]);
                }
            }
            if (jnext < NOC * 8) {
                issue_Aw(wbuf, lane, woff, warp_m, jnext);
                jnext++;
            }
            CP_COMMIT();   // unconditional: empty tail groups keep wait(1) safe
        }

        // ---- epilogue for this oc block ----
        const int oc0 = ob * 128;
        #pragma unroll
        for (int mt = 0; mt < 2; mt++) {
            const int mBase = warp_m * 32 + mt * 16 + (lane >> 2);
            #pragma unroll
            for (int oct = 0; oct < 8; oct++) {
                const int n = warp_n * 64 + oct * 8 + 2 * (lane & 3);
                const float* d = acc[mt][oct];
                #pragma unroll
                for (int rr = 0; rr < 2; rr++) {
                    const int oc = oc0 + mBase + rr * 8;
                    float v0 = d[rr * 2 + 0];
                    float v1 = d[rr * 2 + 1];
                    if (MODE == 2) {
                        const float bs = bias[oc];
                        // n = jw*64 + l; window nw0+jw; l -> (h,w) in window
                        const int nw = nw0 + (n >> 6);
                        const int l  = n & 63;
                        const int bo2 = nw >> 10;
                        const int hw  = (nw >> 5) & 31;
                        const int ww  = nw & 31;
                        const int hh  = hw * 8 + (l >> 3);
                        const int wwp = ww * 8 + (l & 7);
                        if (hh < HH) {
                            if (wwp < WW)
                                Out[((size_t)(bo2 * 256 + oc) * HH + hh) * WW + wwp] = v0 + bs;
                            if (wwp + 1 < WW)
                                Out[((size_t)(bo2 * 256 + oc) * HH + hh) * WW + wwp + 1] = v1 + bs;
                        }
                    } else {
                        if (MODE == 0) {
                            v0 *= 0.1767766952966369f;   // fold softmax scale into Q
                            v1 *= 0.1767766952966369f;
                        }
                        const int w  = w0 + n;
                        const int nw = (b * 32 + (h >> 3)) * 32 + (w >> 3);
                        const int l  = ((h & 7) << 3) | (w & 7);
                        const int cc = oc & 255;
                        const int idx2 = (((nw * 8 + (cc >> 5)) * 32 + (cc & 31)) * 64 + l) >> 1;
                        uint32_t* dst;
                        if (MODE == 0)     dst = reinterpret_cast<uint32_t*>(g_Q);
                        else if (ob < 2)   dst = reinterpret_cast<uint32_t*>(g_K);
                        else               dst = reinterpret_cast<uint32_t*>(g_V);
                        dst[idx2] = pack_half(v0, v1);
                    }
                }
            }
        }
    }
}

// ---------------------------------------------------------------------------
// fp16 MMA attention: block = 128 threads = 2 window-heads, 2 warps per wh.
// Output written as O slab [wh][d][l] via smem transpose + coalesced STG.
// ---------------------------------------------------------------------------
#define SLAB 4608                 // 32 rows * 144B
#define WHSZ (3 * SLAB)           // Q K V
#define O_OFF (2 * WHSZ)          // 27648
#define O_PITCH 144
#define O_WH (32 * O_PITCH)       // 4608
#define ATT_SMEM (O_OFF + 2 * O_WH)   // 36864

__global__ __launch_bounds__(128)
void attn_mma()
{
    extern __shared__ char smem[];
    const int tid  = threadIdx.x;
    const int wid  = tid >> 5;
    const int lane = tid & 31;

    const __half* srcs[3] = {g_Q, g_K, g_V};
    #pragma unroll
    for (int sl = 0; sl < 2; sl++) {
        const size_t gbase = (size_t)(blockIdx.x * 2 + sl) * 2048;
        #pragma unroll
        for (int a = 0; a < 3; a++) {
            const uint4* src = reinterpret_cast<const uint4*>(srcs[a] + gbase);
            char* dstb = smem + sl * WHSZ + a * SLAB;
            #pragma unroll
            for (int i = 0; i < 2; i++) {
                const int idx = i * 128 + tid;
                const uint4 v = src[idx];
                *reinterpret_cast<uint4*>(dstb + (idx >> 3) * 144 + (idx & 7) * 16) = v;
            }
        }
    }
    __syncthreads();

    const uint32_t sb = smem_u32(smem) + (wid >> 1) * WHSZ;
    const uint32_t uQ = sb, uK = sb + SLAB, uV = sb + 2 * SLAB;
    const int whalf = wid & 1;

    const int g = lane >> 2;
    const int t = lane & 3;

    char* obase = smem + O_OFF + (wid >> 1) * O_WH;

    const uint32_t qRow = (uint32_t)((lane & 7) + ((lane >> 4) & 1) * 8);
    const uint32_t qCol = (uint32_t)(((lane >> 3) & 1) * 16);
    const uint32_t kRow = (uint32_t)((lane & 7) + ((lane >> 3) & 1) * 8);
    const uint32_t kCol = (uint32_t)((lane >> 4) * 16);
    const uint32_t vRow = (uint32_t)((lane & 7) + ((lane >> 4) & 1) * 8);
    const uint32_t vCol = (uint32_t)(((lane >> 3) & 1) * 16);

    #pragma unroll
    for (int mt = 0; mt < 2; mt++) {
        const int ltile = whalf * 2 + mt;

        float s[8][4];
        #pragma unroll
        for (int j = 0; j < 8; j++)
            #pragma unroll
            for (int k = 0; k < 4; k++) s[j][k] = 0.f;

        #pragma unroll
        for (int kt = 0; kt < 2; kt++) {
            uint32_t ah[4];
            const uint32_t ao = (qRow + kt * 16) * 144 + qCol + (uint32_t)(ltile * 32);
            LDSM_X4_T(ah[0], ah[1], ah[2], ah[3], uQ + ao);
            #pragma unroll
            for (int nt = 0; nt < 4; nt++) {
                uint32_t bh[4];
                const uint32_t bo = (kRow + kt * 16) * 144 + kCol + (uint32_t)(nt * 32);
                LDSM_X4_T(bh[0], bh[1], bh[2], bh[3], uK + bo);
                #pragma unroll
                for (int half = 0; half < 2; half++)
                    mma_f16(s[nt * 2 + half], ah, bh[half * 2], bh[half * 2 + 1]);
            }
        }

        float mx0 = -1e30f, mx1 = -1e30f;
        #pragma unroll
        for (int j = 0; j < 8; j++) {
            mx0 = fmaxf(mx0, fmaxf(s[j][0], s[j][1]));
            mx1 = fmaxf(mx1, fmaxf(s[j][2], s[j][3]));
        }
        mx0 = fmaxf(mx0, __shfl_xor_sync(0xffffffffu, mx0, 1));
        mx0 = fmaxf(mx0, __shfl_xor_sync(0xffffffffu, mx0, 2));
        mx1 = fmaxf(mx1, __shfl_xor_sync(0xffffffffu, mx1, 1));
        mx1 = fmaxf(mx1, __shfl_xor_sync(0xffffffffu, mx1, 2));

        float sum0 = 0.f, sum1 = 0.f;
        uint32_t ph01[8], ph23[8];
        #pragma unroll
        for (int j = 0; j < 8; j++) {
            const float e0 = __expf(s[j][0] - mx0);
            const float e1 = __expf(s[j][1] - mx0);
            const float e2 = __expf(s[j][2] - mx1);
            const float e3 = __expf(s[j][3] - mx1);
            sum0 += e0 + e1;
            sum1 += e2 + e3;
            ph01[j] = pack_half(e0, e1);
            ph23[j] = pack_half(e2, e3);
        }
        sum0 += __shfl_xor_sync(0xffffffffu, sum0, 1);
        sum0 += __shfl_xor_sync(0xffffffffu, sum0, 2);
        sum1 += __shfl_xor_sync(0xffffffffu, sum1, 1);
        sum1 += __shfl_xor_sync(0xffffffffu, sum1, 2);
        const float inv0 = 1.f / sum0;
        const float inv1 = 1.f / sum1;

        float o[4][4];
        #pragma unroll
        for (int j = 0; j < 4; j++)
            #pragma unroll
            for (int k = 0; k < 4; k++) o[j][k] = 0.f;

        #pragma unroll
        for (int kt = 0; kt < 4; kt++) {
            uint32_t ap[4];
            ap[0] = ph01[2 * kt];     ap[1] = ph23[2 * kt];
            ap[2] = ph01[2 * kt + 1]; ap[3] = ph23[2 * kt + 1];
            #pragma unroll
            for (int dt2 = 0; dt2 < 2; dt2++) {
                uint32_t bh[4];
                const uint32_t bo = (vRow + dt2 * 16) * 144 + vCol + (uint32_t)(kt * 32);
                LDSM_X4(bh[0], bh[1], bh[2], bh[3], uV + bo);
                #pragma unroll
                for (int half = 0; half < 2; half++)
                    mma_f16(o[dt2 * 2 + half], ap, bh[half * 2], bh[half * 2 + 1]);
            }
        }

        // ---- store O frags to smem [d][l] (pitch 144) ----
        const int l0 = ltile * 16 + g;
        const int l1 = l0 + 8;
        #pragma unroll
        for (int dt = 0; dt < 4; dt++) {
            const int d0 = dt * 8 + 2 * t;
            *(__half*)(obase + d0 * O_PITCH + l0 * 2)
                = __float2half_rn(o[dt][0] * inv0);
            *(__half*)(obase + (d0 + 1) * O_PITCH + l0 * 2)
                = __float2half_rn(o[dt][1] * inv0);
            *(__half*)(obase + d0 * O_PITCH + l1 * 2)
                = __float2half_rn(o[dt][2] * inv1);
            *(__half*)(obase + (d0 + 1) * O_PITCH + l1 * 2)
                = __float2half_rn(o[dt][3] * inv1);
        }
    }

    // ---- coalesced slab write: 2 wh x 2048 halves ----
    __syncthreads();
    const size_t og = (size_t)blockIdx.x * 4096;
    #pragma unroll
    for (int i = 0; i < 4; i++) {
        const int u = i * 128 + tid;          // 0..511 uint4
        const int whs = u >> 8;
        const int rm  = u & 255;
        const int d = rm >> 3, j = rm & 7;
        const uint4 v = *reinterpret_cast<const uint4*>(
            smem + O_OFF + whs * O_WH + d * O_PITCH + j * 16);
        *reinterpret_cast<uint4*>(g_O + og + whs * 2048 + d * 64 + j * 8) = v;
    }
}

// ---------------------------------------------------------------------------
extern "C" void kernel_launch(void* const* d_in, const int* in_sizes, int n_in,
                              void* d_out, int out_size)
{
    const float* x_q    = (const float*)d_in[0];
    const float* x_kv   = (const float*)d_in[1];
    const float* w_q    = (const float*)d_in[2];
    const float* w_kv   = (const float*)d_in[3];
    const float* w_proj = (const float*)d_in[4];
    const float* b_proj = (const float*)d_in[5];
    float* out = (float*)d_out;

    cudaFuncSetAttribute(attn_mma, cudaFuncAttributeMaxDynamicSharedMemorySize, ATT_SMEM);
    cudaFuncSetAttribute(proj_v8<0>, cudaFuncAttributeMaxDynamicSharedMemorySize, P_SMEM);
    cudaFuncSetAttribute(proj_v8<1>, cudaFuncAttributeMaxDynamicSharedMemorySize, P_SMEM);
    cudaFuncSetAttribute(proj_v8<2>, cudaFuncAttributeMaxDynamicSharedMemorySize, P_SMEM);

    __half* oi;
    cudaGetSymbolAddress((void**)&oi, g_O);

    prep_w<<<1024, 256>>>(w_q, w_kv, w_proj);

    const int pixTiles = (BB * HP * WP) / 128;   // 2048
    proj_v8<0><<<pixTiles, 256, P_SMEM>>>(x_q,  0,      nullptr, nullptr);
    proj_v8<1><<<pixTiles, 256, P_SMEM>>>(x_kv, 65536,  nullptr, nullptr);
    attn_mma<<<16384, 128, ATT_SMEM>>>();
    proj_v8<2><<<pixTiles, 256, P_SMEM>>>(oi, 196608, b_proj, out);
}

// round 16
// speedup vs baseline: 1.0858x; 1.0547x over previous
#include <cuda_runtime.h>
#include <cuda_fp16.h>
#include <cstdint>
#include <math.h>

// Problem constants
#define BB 4
#define CC 256
#define HH 252
#define WW 252
#define HP 256
#define WP 256

// Q/K/V and attention-output slabs, fp16, layout [wh=32768][d=32][pix=64]
__device__ __half g_Q[67108864];
__device__ __half g_K[67108864];
__device__ __half g_V[67108864];
__device__ __half g_O[67108864];
// fp16 weights: wq(256x256) | wkv(512x256) | wproj(256x256)
__device__ __half g_W[262144];

// ---------------------------------------------------------------------------
__device__ __forceinline__ uint32_t smem_u32(const void* p) {
    uint32_t a;
    asm("{ .reg .u64 t; cvta.to.shared.u64 t, %1; cvt.u32.u64 %0, t; }"
        : "=r"(a) : "l"(p));
    return a;
}
#define LDSM_X4(r0, r1, r2, r3, addr)                                          \
    asm volatile("ldmatrix.sync.aligned.m8n8.x4.shared.b16 {%0,%1,%2,%3}, [%4];" \
                 : "=r"(r0), "=r"(r1), "=r"(r2), "=r"(r3) : "r"(addr))
#define LDSM_X4_T(r0, r1, r2, r3, addr)                                        \
    asm volatile("ldmatrix.sync.aligned.m8n8.x4.trans.shared.b16 {%0,%1,%2,%3}, [%4];" \
                 : "=r"(r0), "=r"(r1), "=r"(r2), "=r"(r3) : "r"(addr))
__device__ __forceinline__ void mma_f16(float* d, const uint32_t* a,
                                        uint32_t b0, uint32_t b1) {
    asm volatile(
        "mma.sync.aligned.m16n8k16.row.col.f32.f16.f16.f32 "
        "{%0,%1,%2,%3}, {%4,%5,%6,%7}, {%8,%9}, {%0,%1,%2,%3};"
        : "+f"(d[0]), "+f"(d[1]), "+f"(d[2]), "+f"(d[3])
        : "r"(a[0]), "r"(a[1]), "r"(a[2]), "r"(a[3]), "r"(b0), "r"(b1));
}
__device__ __forceinline__ uint32_t pack_half(float a, float b) {
    __half2 v;
    v.x = __float2half_rn(a);
    v.y = __float2half_rn(b);
    return *reinterpret_cast<uint32_t*>(&v);
}
__device__ __forceinline__ void cpa16(uint32_t dst, const void* src) {
    asm volatile("cp.async.cg.shared.global [%0], [%1], 16;" :: "r"(dst), "l"(src));
}
#define CP_COMMIT() asm volatile("cp.async.commit_group;" ::: "memory")
#define CP_WAIT(n)  asm volatile("cp.async.wait_group %0;" :: "n"(n) : "memory")

// ---------------------------------------------------------------------------
__global__ void prep_w(const float* __restrict__ wq, const float* __restrict__ wkv,
                       const float* __restrict__ wproj)
{
    int i = blockIdx.x * 256 + threadIdx.x;
    float v;
    if (i < 65536)       v = wq[i];
    else if (i < 196608) v = wkv[i - 65536];
    else                 v = wproj[i - 196608];
    g_W[i] = __float2half_rn(v);
}

// ---------------------------------------------------------------------------
// Shared proj machinery (R15 design): B-resident + warp-private A staging,
// barrier-free mainloop.
// ---------------------------------------------------------------------------
#define PB_PITCH 272
#define PB_BYTES (256 * PB_PITCH)            // 69632
#define PA_OFF   PB_BYTES
#define PA_WSTG  2560                        // 32 rows * 80B (pitch-padded)
#define PA_WARP  (2 * PA_WSTG)               // 2 stages per warp
#define P_SMEM   (PA_OFF + 8 * PA_WARP)      // 110592

__device__ __forceinline__ void issue_Aw(
    uint32_t wbuf, int lane, int woff, int warp_m, int jchunk)
{
    const int oc0 = (jchunk >> 3) * 128;
    const int k0  = (jchunk & 7) * 32;
    const uint32_t st = wbuf + (uint32_t)(jchunk & 1) * PA_WSTG;
    #pragma unroll
    for (int it = 0; it < 4; it++) {
        const int idx = it * 32 + lane;      // 0..127 (16B units)
        const int row = idx >> 2;            // 0..31
        const int j   = idx & 3;             // 0..3 (8 halves each)
        cpa16(st + (uint32_t)(row * 80 + j * 16),
              g_W + woff + (oc0 + warp_m * 32 + row) * 256 + k0 + j * 8);
    }
}

// ---------------------------------------------------------------------------
// Fused Q + KV projection: grid 4096. Blocks [0,2048): Q proj on x_q (NOC=2);
// blocks [2048,4096): KV proj on x_kv (NOC=4). fp32->fp16 conversion fused
// into the B staging.
// ---------------------------------------------------------------------------
__global__ __launch_bounds__(256, 2)
void proj_qkv(const float* __restrict__ xq, const float* __restrict__ xkv)
{
    extern __shared__ char smem[];
    const uint32_t sb = smem_u32(smem);

    const int kv   = (blockIdx.x >= 2048) ? 1 : 0;
    const int bx   = blockIdx.x & 2047;
    const int NOC  = kv ? 4 : 2;
    const int woff = kv ? 65536 : 0;
    const float* Xf = kv ? xkv : xq;

    const int tid  = threadIdx.x;
    const int wid  = tid >> 5;
    const int lane = tid & 31;
    const int warp_m = wid & 3;
    const int warp_n = wid >> 2;

    const int p0  = bx * 128;
    const int b   = p0 >> 16;
    const int rem = p0 & 65535;
    const int h   = rem >> 8;
    const int w0  = rem & 255;

    const uint32_t wbuf = sb + PA_OFF + (uint32_t)(wid * PA_WARP);

    // ---- prologue: stage full B column with inline fp32->fp16 ----
    #pragma unroll 8
    for (int it = 0; it < 32; it++) {
        const int idx = it * 256 + tid;      // 0..8191 (float4 units)
        const int c = idx >> 5;              // channel 0..255
        const int q = idx & 31;              // float4 index (px = 4q)
        float4 v = make_float4(0.f, 0.f, 0.f, 0.f);
        if (h < HH && (w0 + q * 4) < WW)
            v = *reinterpret_cast<const float4*>(
                &Xf[((size_t)(b * 256 + c) * HH + h) * WW + w0 + q * 4]);
        uint2 p;
        p.x = pack_half(v.x, v.y);
        p.y = pack_half(v.z, v.w);
        *reinterpret_cast<uint2*>(smem + c * PB_PITCH + q * 8) = p;
    }
    issue_Aw(wbuf, lane, woff, warp_m, 0); CP_COMMIT();
    issue_Aw(wbuf, lane, woff, warp_m, 1); CP_COMMIT();
    __syncthreads();             // the ONLY CTA barrier
    int jnext = 2;

    const uint32_t bLaneOff = (uint32_t)(((lane & 7) + ((lane >> 3) & 1) * 8) * PB_PITCH
                                         + (warp_n * 64 + (lane >> 4) * 8) * 2);
    const uint32_t aLaneOff = (uint32_t)((lane & 15) * 80 + (lane >> 4) * 16);

    for (int ob = 0; ob < NOC; ob++) {
        float acc[2][8][4];
        #pragma unroll
        for (int i = 0; i < 2; i++)
            #pragma unroll
            for (int j = 0; j < 8; j++)
                #pragma unroll
                for (int k = 0; k < 4; k++) acc[i][j][k] = 0.f;

        for (int ch = 0; ch < 8; ch++) {
            const int jcur = ob * 8 + ch;
            CP_WAIT(1);
            __syncwarp();

            const uint32_t uA = wbuf + (uint32_t)(jcur & 1) * PA_WSTG;

            #pragma unroll
            for (int s = 0; s < 2; s++) {
                uint32_t bh[4][4];
                #pragma unroll
                for (int np = 0; np < 4; np++) {
                    const uint32_t bo = bLaneOff
                        + (uint32_t)((ch * 32 + s * 16) * PB_PITCH + np * 32);
                    LDSM_X4_T(bh[np][0], bh[np][1], bh[np][2], bh[np][3], sb + bo);
                }
                #pragma unroll
                for (int mt = 0; mt < 2; mt++) {
                    uint32_t ah[4];
                    const uint32_t ao = aLaneOff + (uint32_t)(mt * 16 * 80 + s * 32);
                    LDSM_X4(ah[0], ah[1], ah[2], ah[3], uA + ao);
                    #pragma unroll
                    for (int np = 0; np < 4; np++)
                        #pragma unroll
                        for (int half = 0; half < 2; half++)
                            mma_f16(acc[mt][np * 2 + half], ah,
                                    bh[np][half * 2], bh[np][half * 2 + 1]);
                }
            }
            if (jnext < NOC * 8) {
                issue_Aw(wbuf, lane, woff, warp_m, jnext);
                jnext++;
            }
            CP_COMMIT();   // unconditional: empty tail groups keep wait(1) safe
        }

        // ---- epilogue for this oc block: slab scatter ----
        const int oc0 = ob * 128;
        uint32_t* dst;
        if (!kv)          dst = reinterpret_cast<uint32_t*>(g_Q);
        else if (ob < 2)  dst = reinterpret_cast<uint32_t*>(g_K);
        else              dst = reinterpret_cast<uint32_t*>(g_V);
        #pragma unroll
        for (int mt = 0; mt < 2; mt++) {
            const int mBase = warp_m * 32 + mt * 16 + (lane >> 2);
            #pragma unroll
            for (int oct = 0; oct < 8; oct++) {
                const int n = warp_n * 64 + oct * 8 + 2 * (lane & 3);
                const float* d = acc[mt][oct];
                #pragma unroll
                for (int rr = 0; rr < 2; rr++) {
                    const int oc = oc0 + mBase + rr * 8;
                    float v0 = d[rr * 2 + 0];
                    float v1 = d[rr * 2 + 1];
                    if (!kv) {
                        v0 *= 0.1767766952966369f;   // fold softmax scale into Q
                        v1 *= 0.1767766952966369f;
                    }
                    const int w  = w0 + n;
                    const int nw = (b * 32 + (h >> 3)) * 32 + (w >> 3);
                    const int l  = ((h & 7) << 3) | (w & 7);
                    const int cc = oc & 255;
                    const int idx2 = (((nw * 8 + (cc >> 5)) * 32 + (cc & 31)) * 64 + l) >> 1;
                    dst[idx2] = pack_half(v0, v1);
                }
            }
        }
    }
}

// ---------------------------------------------------------------------------
// proj_out: final projection. Pixel tile = TWO whole windows (2 x 64 l);
// B staged from the O slab via fully contiguous 128B rows per channel.
// ---------------------------------------------------------------------------
__global__ __launch_bounds__(256, 2)
void proj_out(const float* __restrict__ bias, float* __restrict__ Out)
{
    constexpr int NOC = 2;
    extern __shared__ char smem[];
    const uint32_t sb = smem_u32(smem);

    const int tid  = threadIdx.x;
    const int wid  = tid >> 5;
    const int lane = tid & 31;
    const int warp_m = wid & 3;
    const int warp_n = wid >> 2;

    const int nw0 = blockIdx.x * 2;
    const int woff = 196608;

    const uint32_t wbuf = sb + PA_OFF + (uint32_t)(wid * PA_WARP);

    // ---- prologue: per channel, 2 x 128B contiguous slab rows ----
    #pragma unroll
    for (int it = 0; it < 16; it++) {
        const int idx = it * 256 + tid;      // 0..4095, 16B each
        const int c  = idx >> 4;
        const int jw = (idx >> 3) & 1;       // which window
        const int j  = idx & 7;              // 16B line within the row
        cpa16(sb + (uint32_t)(c * PB_PITCH + jw * 128 + j * 16),
              g_O + ((((nw0 + jw) * 8 + (c >> 5)) * 32 + (c & 31)) * 64 + j * 8));
    }
    CP_COMMIT();
    issue_Aw(wbuf, lane, woff, warp_m, 0); CP_COMMIT();
    issue_Aw(wbuf, lane, woff, warp_m, 1); CP_COMMIT();
    CP_WAIT(2);                 // B group done; A0/A1 pending
    __syncthreads();            // the ONLY CTA barrier
    int jnext = 2;

    const uint32_t bLaneOff = (uint32_t)(((lane & 7) + ((lane >> 3) & 1) * 8) * PB_PITCH
                                         + (warp_n * 64 + (lane >> 4) * 8) * 2);
    const uint32_t aLaneOff = (uint32_t)((lane & 15) * 80 + (lane >> 4) * 16);

    for (int ob = 0; ob < NOC; ob++) {
        float acc[2][8][4];
        #pragma unroll
        for (int i = 0; i < 2; i++)
            #pragma unroll
            for (int j = 0; j < 8; j++)
                #pragma unroll
                for (int k = 0; k < 4; k++) acc[i][j][k] = 0.f;

        for (int ch = 0; ch < 8; ch++) {
            const int jcur = ob * 8 + ch;
            CP_WAIT(1);
            __syncwarp();

            const uint32_t uA = wbuf + (uint32_t)(jcur & 1) * PA_WSTG;

            #pragma unroll
            for (int s = 0; s < 2; s++) {
                uint32_t bh[4][4];
                #pragma unroll
                for (int np = 0; np < 4; np++) {
                    const uint32_t bo = bLaneOff
                        + (uint32_t)((ch * 32 + s * 16) * PB_PITCH + np * 32);
                    LDSM_X4_T(bh[np][0], bh[np][1], bh[np][2], bh[np][3], sb + bo);
                }
                #pragma unroll
                for (int mt = 0; mt < 2; mt++) {
                    uint32_t ah[4];
                    const uint32_t ao = aLaneOff + (uint32_t)(mt * 16 * 80 + s * 32);
                    LDSM_X4(ah[0], ah[1], ah[2], ah[3], uA + ao);
                    #pragma unroll
                    for (int np = 0; np < 4; np++)
                        #pragma unroll
                        for (int half = 0; half < 2; half++)
                            mma_f16(acc[mt][np * 2 + half], ah,
                                    bh[np][half * 2], bh[np][half * 2 + 1]);
                }
            }
            if (jnext < NOC * 8) {
                issue_Aw(wbuf, lane, woff, warp_m, jnext);
                jnext++;
            }
            CP_COMMIT();
        }

        // ---- epilogue: cropped image write + bias ----
        const int oc0 = ob * 128;
        #pragma unroll
        for (int mt = 0; mt < 2; mt++) {
            const int mBase = warp_m * 32 + mt * 16 + (lane >> 2);
            #pragma unroll
            for (int oct = 0; oct < 8; oct++) {
                const int n = warp_n * 64 + oct * 8 + 2 * (lane & 3);
                const float* d = acc[mt][oct];
                #pragma unroll
                for (int rr = 0; rr < 2; rr++) {
                    const int oc = oc0 + mBase + rr * 8;
                    const float bs = bias[oc];
                    const int nw = nw0 + (n >> 6);
                    const int l  = n & 63;
                    const int bo2 = nw >> 10;
                    const int hw  = (nw >> 5) & 31;
                    const int ww  = nw & 31;
                    const int hh  = hw * 8 + (l >> 3);
                    const int wwp = ww * 8 + (l & 7);
                    if (hh < HH) {
                        if (wwp < WW)
                            Out[((size_t)(bo2 * 256 + oc) * HH + hh) * WW + wwp]
                                = d[rr * 2 + 0] + bs;
                        if (wwp + 1 < WW)
                            Out[((size_t)(bo2 * 256 + oc) * HH + hh) * WW + wwp + 1]
                                = d[rr * 2 + 1] + bs;
                    }
                }
            }
        }
    }
}

// ---------------------------------------------------------------------------
// fp16 MMA attention: block = 128 threads = 2 window-heads, 2 warps per wh.
// Staging via cp.async; output to O slab via smem transpose + coalesced STG.
// ---------------------------------------------------------------------------
#define SLAB 4608                 // 32 rows * 144B
#define WHSZ (3 * SLAB)           // Q K V
#define O_OFF (2 * WHSZ)          // 27648
#define O_PITCH 144
#define O_WH (32 * O_PITCH)       // 4608
#define ATT_SMEM (O_OFF + 2 * O_WH)   // 36864

__global__ __launch_bounds__(128)
void attn_mma()
{
    extern __shared__ char smem[];
    const uint32_t sbase = smem_u32(smem);
    const int tid  = threadIdx.x;
    const int wid  = tid >> 5;
    const int lane = tid & 31;

    const __half* srcs[3] = {g_Q, g_K, g_V};
    #pragma unroll
    for (int sl = 0; sl < 2; sl++) {
        const size_t gbase = (size_t)(blockIdx.x * 2 + sl) * 2048;
        #pragma unroll
        for (int a = 0; a < 3; a++) {
            const __half* src = srcs[a] + gbase;
            const uint32_t dstb = sbase + (uint32_t)(sl * WHSZ + a * SLAB);
            #pragma unroll
            for (int i = 0; i < 2; i++) {
                const int idx = i * 128 + tid;           // 0..255, 16B each
                cpa16(dstb + (uint32_t)((idx >> 3) * 144 + (idx & 7) * 16),
                      src + idx * 8);
            }
        }
    }
    CP_COMMIT();
    CP_WAIT(0);
    __syncthreads();

    const uint32_t sb = sbase + (wid >> 1) * WHSZ;
    const uint32_t uQ = sb, uK = sb + SLAB, uV = sb + 2 * SLAB;
    const int whalf = wid & 1;

    const int g = lane >> 2;
    const int t = lane & 3;

    char* obase = smem + O_OFF + (wid >> 1) * O_WH;

    const uint32_t qRow = (uint32_t)((lane & 7) + ((lane >> 4) & 1) * 8);
    const uint32_t qCol = (uint32_t)(((lane >> 3) & 1) * 16);
    const uint32_t kRow = (uint32_t)((lane & 7) + ((lane >> 3) & 1) * 8);
    const uint32_t kCol = (uint32_t)((lane >> 4) * 16);
    const uint32_t vRow = (uint32_t)((lane & 7) + ((lane >> 4) & 1) * 8);
    const uint32_t vCol = (uint32_t)(((lane >> 3) & 1) * 16);

    #pragma unroll
    for (int mt = 0; mt < 2; mt++) {
        const int ltile = whalf * 2 + mt;

        float s[8][4];
        #pragma unroll
        for (int j = 0; j < 8; j++)
            #pragma unroll
            for (int k = 0; k < 4; k++) s[j][k] = 0.f;

        #pragma unroll
        for (int kt = 0; kt < 2; kt++) {
            uint32_t ah[4];
            const uint32_t ao = (qRow + kt * 16) * 144 + qCol + (uint32_t)(ltile * 32);
            LDSM_X4_T(ah[0], ah[1], ah[2], ah[3], uQ + ao);
            #pragma unroll
            for (int nt = 0; nt < 4; nt++) {
                uint32_t bh[4];
                const uint32_t bo = (kRow + kt * 16) * 144 + kCol + (uint32_t)(nt * 32);
                LDSM_X4_T(bh[0], bh[1], bh[2], bh[3], uK + bo);
                #pragma unroll
                for (int half = 0; half < 2; half++)
                    mma_f16(s[nt * 2 + half], ah, bh[half * 2], bh[half * 2 + 1]);
            }
        }

        float mx0 = -1e30f, mx1 = -1e30f;
        #pragma unroll
        for (int j = 0; j < 8; j++) {
            mx0 = fmaxf(mx0, fmaxf(s[j][0], s[j][1]));
            mx1 = fmaxf(mx1, fmaxf(s[j][2], s[j][3]));
        }
        mx0 = fmaxf(mx0, __shfl_xor_sync(0xffffffffu, mx0, 1));
        mx0 = fmaxf(mx0, __shfl_xor_sync(0xffffffffu, mx0, 2));
        mx1 = fmaxf(mx1, __shfl_xor_sync(0xffffffffu, mx1, 1));
        mx1 = fmaxf(mx1, __shfl_xor_sync(0xffffffffu, mx1, 2));

        float sum0 = 0.f, sum1 = 0.f;
        uint32_t ph01[8], ph23[8];
        #pragma unroll
        for (int j = 0; j < 8; j++) {
            const float e0 = __expf(s[j][0] - mx0);
            const float e1 = __expf(s[j][1] - mx0);
            const float e2 = __expf(s[j][2] - mx1);
            const float e3 = __expf(s[j][3] - mx1);
            sum0 += e0 + e1;
            sum1 += e2 + e3;
            ph01[j] = pack_half(e0, e1);
            ph23[j] = pack_half(e2, e3);
        }
        sum0 += __shfl_xor_sync(0xffffffffu, sum0, 1);
        sum0 += __shfl_xor_sync(0xffffffffu, sum0, 2);
        sum1 += __shfl_xor_sync(0xffffffffu, sum1, 1);
        sum1 += __shfl_xor_sync(0xffffffffu, sum1, 2);
        const float inv0 = 1.f / sum0;
        const float inv1 = 1.f / sum1;

        float o[4][4];
        #pragma unroll
        for (int j = 0; j < 4; j++)
            #pragma unroll
            for (int k = 0; k < 4; k++) o[j][k] = 0.f;

        #pragma unroll
        for (int kt = 0; kt < 4; kt++) {
            uint32_t ap[4];
            ap[0] = ph01[2 * kt];     ap[1] = ph23[2 * kt];
            ap[2] = ph01[2 * kt + 1]; ap[3] = ph23[2 * kt + 1];
            #pragma unroll
            for (int dt2 = 0; dt2 < 2; dt2++) {
                uint32_t bh[4];
                const uint32_t bo = (vRow + dt2 * 16) * 144 + vCol + (uint32_t)(kt * 32);
                LDSM_X4(bh[0], bh[1], bh[2], bh[3], uV + bo);
                #pragma unroll
                for (int half = 0; half < 2; half++)
                    mma_f16(o[dt2 * 2 + half], ap, bh[half * 2], bh[half * 2 + 1]);
            }
        }

        // ---- store O frags to smem [d][l] (pitch 144) ----
        const int l0 = ltile * 16 + g;
        const int l1 = l0 + 8;
        #pragma unroll
        for (int dt = 0; dt < 4; dt++) {
            const int d0 = dt * 8 + 2 * t;
            *(__half*)(obase + d0 * O_PITCH + l0 * 2)
                = __float2half_rn(o[dt][0] * inv0);
            *(__half*)(obase + (d0 + 1) * O_PITCH + l0 * 2)
                = __float2half_rn(o[dt][1] * inv0);
            *(__half*)(obase + d0 * O_PITCH + l1 * 2)
                = __float2half_rn(o[dt][2] * inv1);
            *(__half*)(obase + (d0 + 1) * O_PITCH + l1 * 2)
                = __float2half_rn(o[dt][3] * inv1);
        }
    }

    // ---- coalesced slab write: 2 wh x 2048 halves ----
    __syncthreads();
    const size_t og = (size_t)blockIdx.x * 4096;
    #pragma unroll
    for (int i = 0; i < 4; i++) {
        const int u = i * 128 + tid;          // 0..511 uint4
        const int whs = u >> 8;
        const int rm  = u & 255;
        const int d = rm >> 3, j = rm & 7;
        const uint4 v = *reinterpret_cast<const uint4*>(
            smem + O_OFF + whs * O_WH + d * O_PITCH + j * 16);
        *reinterpret_cast<uint4*>(g_O + og + whs * 2048 + d * 64 + j * 8) = v;
    }
}

// ---------------------------------------------------------------------------
extern "C" void kernel_launch(void* const* d_in, const int* in_sizes, int n_in,
                              void* d_out, int out_size)
{
    const float* x_q    = (const float*)d_in[0];
    const float* x_kv   = (const float*)d_in[1];
    const float* w_q    = (const float*)d_in[2];
    const float* w_kv   = (const float*)d_in[3];
    const float* w_proj = (const float*)d_in[4];
    const float* b_proj = (const float*)d_in[5];
    float* out = (float*)d_out;

    cudaFuncSetAttribute(attn_mma, cudaFuncAttributeMaxDynamicSharedMemorySize, ATT_SMEM);
    cudaFuncSetAttribute(proj_qkv, cudaFuncAttributeMaxDynamicSharedMemorySize, P_SMEM);
    cudaFuncSetAttribute(proj_out, cudaFuncAttributeMaxDynamicSharedMemorySize, P_SMEM);

    prep_w<<<1024, 256>>>(w_q, w_kv, w_proj);

    proj_qkv<<<4096, 256, P_SMEM>>>(x_q, x_kv);
    attn_mma<<<16384, 128, ATT_SMEM>>>();
    proj_out<<<2048, 256, P_SMEM>>>(b_proj, out);
}

// round 17
// speedup vs baseline: 1.1034x; 1.0162x over previous
#include <cuda_runtime.h>
#include <cuda_fp16.h>
#include <cstdint>
#include <math.h>

// Problem constants
#define BB 4
#define CC 256
#define HH 252
#define WW 252
#define HP 256
#define WP 256

// Q/K/V and attention-output slabs, fp16, layout [wh=32768][d=32][pix=64]
__device__ __half g_Q[67108864];
__device__ __half g_K[67108864];
__device__ __half g_V[67108864];
__device__ __half g_O[67108864];
// fp16 weights: wq(256x256) | wkv(512x256) | wproj(256x256)
__device__ __half g_W[262144];

// ---------------------------------------------------------------------------
__device__ __forceinline__ uint32_t smem_u32(const void* p) {
    uint32_t a;
    asm("{ .reg .u64 t; cvta.to.shared.u64 t, %1; cvt.u32.u64 %0, t; }"
        : "=r"(a) : "l"(p));
    return a;
}
#define LDSM_X4(r0, r1, r2, r3, addr)                                          \
    asm volatile("ldmatrix.sync.aligned.m8n8.x4.shared.b16 {%0,%1,%2,%3}, [%4];" \
                 : "=r"(r0), "=r"(r1), "=r"(r2), "=r"(r3) : "r"(addr))
#define LDSM_X4_T(r0, r1, r2, r3, addr)                                        \
    asm volatile("ldmatrix.sync.aligned.m8n8.x4.trans.shared.b16 {%0,%1,%2,%3}, [%4];" \
                 : "=r"(r0), "=r"(r1), "=r"(r2), "=r"(r3) : "r"(addr))
__device__ __forceinline__ void mma_f16(float* d, const uint32_t* a,
                                        uint32_t b0, uint32_t b1) {
    asm volatile(
        "mma.sync.aligned.m16n8k16.row.col.f32.f16.f16.f32 "
        "{%0,%1,%2,%3}, {%4,%5,%6,%7}, {%8,%9}, {%0,%1,%2,%3};"
        : "+f"(d[0]), "+f"(d[1]), "+f"(d[2]), "+f"(d[3])
        : "r"(a[0]), "r"(a[1]), "r"(a[2]), "r"(a[3]), "r"(b0), "r"(b1));
}
__device__ __forceinline__ uint32_t pack_half(float a, float b) {
    __half2 v;
    v.x = __float2half_rn(a);
    v.y = __float2half_rn(b);
    return *reinterpret_cast<uint32_t*>(&v);
}
__device__ __forceinline__ void cpa16(uint32_t dst, const void* src) {
    asm volatile("cp.async.cg.shared.global [%0], [%1], 16;" :: "r"(dst), "l"(src));
}
#define CP_COMMIT() asm volatile("cp.async.commit_group;" ::: "memory")
#define CP_WAIT(n)  asm volatile("cp.async.wait_group %0;" :: "n"(n) : "memory")
#define BAR_PAIR(id) asm volatile("bar.sync %0, 64;" :: "r"(id) : "memory")

// ---------------------------------------------------------------------------
__global__ void prep_w(const float* __restrict__ wq, const float* __restrict__ wkv,
                       const float* __restrict__ wproj)
{
    int i = blockIdx.x * 256 + threadIdx.x;
    float v;
    if (i < 65536)       v = wq[i];
    else if (i < 196608) v = wkv[i - 65536];
    else                 v = wproj[i - 196608];
    g_W[i] = __float2half_rn(v);
}

// ---------------------------------------------------------------------------
// proj engine v9: tile M=128 x N=64, B-resident (36.9KB), A staged in
// PAIR-SHARED warp buffers (warps wid and wid+4 share; producer = wid<4),
// named-barrier pair sync -> 57.3KB smem, 3 CTAs/SM.
// ---------------------------------------------------------------------------
#define PB_PITCH 144
#define PB_BYTES (256 * PB_PITCH)            // 36864
#define PA_OFF   PB_BYTES
#define PA_WSTG  2560                        // 32 rows * 80B (pitch-padded)
#define PA_BUF   (2 * PA_WSTG)               // 2 stages per PAIR
#define P_SMEM   (PA_OFF + 4 * PA_BUF)       // 57344

__device__ __forceinline__ void issue_Aw(
    uint32_t wbuf, int lane, int woff, int warp_m, int jchunk)
{
    const int oc0 = (jchunk >> 3) * 128;
    const int k0  = (jchunk & 7) * 32;
    const uint32_t st = wbuf + (uint32_t)(jchunk & 1) * PA_WSTG;
    #pragma unroll
    for (int it = 0; it < 4; it++) {
        const int idx = it * 32 + lane;      // 0..127 (16B units)
        const int row = idx >> 2;            // 0..31
        const int j   = idx & 3;             // 0..3 (8 halves each)
        cpa16(st + (uint32_t)(row * 80 + j * 16),
              g_W + woff + (oc0 + warp_m * 32 + row) * 256 + k0 + j * 8);
    }
}

// Shared mainloop + epilogue helper is inlined in both kernels below to keep
// the verified code shape identical.

// ---------------------------------------------------------------------------
// Fused Q + KV projection: grid 8192. Blocks [0,4096): Q on x_q (NOC=2);
// [4096,8192): KV on x_kv (NOC=4). 64-px image strips; fp32->fp16 fused.
// ---------------------------------------------------------------------------
__global__ __launch_bounds__(256, 3)
void proj_qkv(const float* __restrict__ xq, const float* __restrict__ xkv)
{
    extern __shared__ char smem[];
    const uint32_t sb = smem_u32(smem);

    const int kv   = (blockIdx.x >= 4096) ? 1 : 0;
    const int bx   = blockIdx.x & 4095;
    const int NOC  = kv ? 4 : 2;
    const int woff = kv ? 65536 : 0;
    const float* Xf = kv ? xkv : xq;

    const int tid  = threadIdx.x;
    const int wid  = tid >> 5;
    const int lane = tid & 31;
    const int warp_m = wid & 3;
    const int warp_n = wid >> 2;
    const bool producer = (warp_n == 0);

    const int p0  = bx * 64;
    const int b   = p0 >> 16;
    const int rem = p0 & 65535;
    const int h   = rem >> 8;
    const int w0  = rem & 255;           // 0,64,128,192

    const uint32_t wbuf = sb + PA_OFF + (uint32_t)(warp_m * PA_BUF);

    // ---- prologue: stage B [256ch][64px] with inline fp32->fp16 ----
    #pragma unroll 4
    for (int it = 0; it < 16; it++) {
        const int idx = it * 256 + tid;      // 0..4095 (float4 units)
        const int c = idx >> 4;              // channel
        const int q = idx & 15;              // float4 (px = 4q)
        float4 v = make_float4(0.f, 0.f, 0.f, 0.f);
        if (h < HH && (w0 + q * 4) < WW)
            v = *reinterpret_cast<const float4*>(
                &Xf[((size_t)(b * 256 + c) * HH + h) * WW + w0 + q * 4]);
        uint2 p;
        p.x = pack_half(v.x, v.y);
        p.y = pack_half(v.z, v.w);
        *reinterpret_cast<uint2*>(smem + c * PB_PITCH + q * 8) = p;
    }
    if (producer) {
        issue_Aw(wbuf, lane, woff, warp_m, 0); CP_COMMIT();
        issue_Aw(wbuf, lane, woff, warp_m, 1); CP_COMMIT();
    }
    __syncthreads();             // B visible CTA-wide
    int jnext = 2;

    const uint32_t bLaneOff = (uint32_t)(((lane & 7) + ((lane >> 3) & 1) * 8) * PB_PITCH
                                         + (warp_n * 32 + (lane >> 4) * 8) * 2);
    const uint32_t aLaneOff = (uint32_t)((lane & 15) * 80 + (lane >> 4) * 16);

    for (int ob = 0; ob < NOC; ob++) {
        float acc[2][4][4];
        #pragma unroll
        for (int i = 0; i < 2; i++)
            #pragma unroll
            for (int j = 0; j < 4; j++)
                #pragma unroll
                for (int k = 0; k < 4; k++) acc[i][j][k] = 0.f;

        for (int ch = 0; ch < 8; ch++) {
            const int jcur = ob * 8 + ch;
            if (producer) CP_WAIT(1);
            BAR_PAIR(1 + warp_m);

            const uint32_t uA = wbuf + (uint32_t)(jcur & 1) * PA_WSTG;

            #pragma unroll
            for (int s = 0; s < 2; s++) {
                uint32_t bh[2][4];
                #pragma unroll
                for (int np = 0; np < 2; np++) {
                    const uint32_t bo = bLaneOff
                        + (uint32_t)((ch * 32 + s * 16) * PB_PITCH + np * 32);
                    LDSM_X4_T(bh[np][0], bh[np][1], bh[np][2], bh[np][3], sb + bo);
                }
                #pragma unroll
                for (int mt = 0; mt < 2; mt++) {
                    uint32_t ah[4];
                    const uint32_t ao = aLaneOff + (uint32_t)(mt * 16 * 80 + s * 32);
                    LDSM_X4(ah[0], ah[1], ah[2], ah[3], uA + ao);
                    #pragma unroll
                    for (int np = 0; np < 2; np++)
                        #pragma unroll
                        for (int half = 0; half < 2; half++)
                            mma_f16(acc[mt][np * 2 + half], ah,
                                    bh[np][half * 2], bh[np][half * 2 + 1]);
                }
            }
            if (producer) {
                if (jnext < NOC * 8) {
                    issue_Aw(wbuf, lane, woff, warp_m, jnext);
                    jnext++;
                }
                CP_COMMIT();   // unconditional: keeps wait(1) safe at tail
            }
        }

        // ---- epilogue: slab scatter ----
        const int oc0 = ob * 128;
        uint32_t* dst;
        if (!kv)          dst = reinterpret_cast<uint32_t*>(g_Q);
        else if (ob < 2)  dst = reinterpret_cast<uint32_t*>(g_K);
        else              dst = reinterpret_cast<uint32_t*>(g_V);
        #pragma unroll
        for (int mt = 0; mt < 2; mt++) {
            const int mBase = warp_m * 32 + mt * 16 + (lane >> 2);
            #pragma unroll
            for (int oct = 0; oct < 4; oct++) {
                const int n = warp_n * 32 + oct * 8 + 2 * (lane & 3);
                const float* d = acc[mt][oct];
                #pragma unroll
                for (int rr = 0; rr < 2; rr++) {
                    const int oc = oc0 + mBase + rr * 8;
                    float v0 = d[rr * 2 + 0];
                    float v1 = d[rr * 2 + 1];
                    if (!kv) {
                        v0 *= 0.1767766952966369f;   // fold softmax scale into Q
                        v1 *= 0.1767766952966369f;
                    }
                    const int w  = w0 + n;
                    const int nw = (b * 32 + (h >> 3)) * 32 + (w >> 3);
                    const int l  = ((h & 7) << 3) | (w & 7);
                    const int cc = oc & 255;
                    const int idx2 = (((nw * 8 + (cc >> 5)) * 32 + (cc & 31)) * 64 + l) >> 1;
                    dst[idx2] = pack_half(v0, v1);
                }
            }
        }
    }
}

// ---------------------------------------------------------------------------
// proj_out: final projection, ONE window per block (64 l). B staged from the
// O slab via fully contiguous 128B rows per channel.
// ---------------------------------------------------------------------------
__global__ __launch_bounds__(256, 3)
void proj_out(const float* __restrict__ bias, float* __restrict__ Out)
{
    constexpr int NOC = 2;
    extern __shared__ char smem[];
    const uint32_t sb = smem_u32(smem);

    const int tid  = threadIdx.x;
    const int wid  = tid >> 5;
    const int lane = tid & 31;
    const int warp_m = wid & 3;
    const int warp_n = wid >> 2;
    const bool producer = (warp_n == 0);

    const int nw  = blockIdx.x;          // window id
    const int woff = 196608;

    const uint32_t wbuf = sb + PA_OFF + (uint32_t)(warp_m * PA_BUF);

    // ---- prologue: per channel, one 128B contiguous slab row ----
    #pragma unroll
    for (int it = 0; it < 8; it++) {
        const int idx = it * 256 + tid;      // 0..2047, 16B each
        const int c = idx >> 3;
        const int j = idx & 7;
        cpa16(sb + (uint32_t)(c * PB_PITCH + j * 16),
              g_O + (((nw * 8 + (c >> 5)) * 32 + (c & 31)) * 64 + j * 8));
    }
    CP_COMMIT();
    if (producer) {
        issue_Aw(wbuf, lane, woff, warp_m, 0); CP_COMMIT();
        issue_Aw(wbuf, lane, woff, warp_m, 1); CP_COMMIT();
        CP_WAIT(2);           // own B group done
    } else {
        CP_WAIT(0);           // own B group done
    }
    __syncthreads();
    int jnext = 2;

    const uint32_t bLaneOff = (uint32_t)(((lane & 7) + ((lane >> 3) & 1) * 8) * PB_PITCH
                                         + (warp_n * 32 + (lane >> 4) * 8) * 2);
    const uint32_t aLaneOff = (uint32_t)((lane & 15) * 80 + (lane >> 4) * 16);

    // window -> image coords
    const int bo2 = nw >> 10;
    const int hw  = (nw >> 5) & 31;
    const int ww  = nw & 31;

    for (int ob = 0; ob < NOC; ob++) {
        float acc[2][4][4];
        #pragma unroll
        for (int i = 0; i < 2; i++)
            #pragma unroll
            for (int j = 0; j < 4; j++)
                #pragma unroll
                for (int k = 0; k < 4; k++) acc[i][j][k] = 0.f;

        for (int ch = 0; ch < 8; ch++) {
            const int jcur = ob * 8 + ch;
            if (producer) CP_WAIT(1);
            BAR_PAIR(1 + warp_m);

            const uint32_t uA = wbuf + (uint32_t)(jcur & 1) * PA_WSTG;

            #pragma unroll
            for (int s = 0; s < 2; s++) {
                uint32_t bh[2][4];
                #pragma unroll
                for (int np = 0; np < 2; np++) {
                    const uint32_t bo = bLaneOff
                        + (uint32_t)((ch * 32 + s * 16) * PB_PITCH + np * 32);
                    LDSM_X4_T(bh[np][0], bh[np][1], bh[np][2], bh[np][3], sb + bo);
                }
                #pragma unroll
                for (int mt = 0; mt < 2; mt++) {
                    uint32_t ah[4];
                    const uint32_t ao = aLaneOff + (uint32_t)(mt * 16 * 80 + s * 32);
                    LDSM_X4(ah[0], ah[1], ah[2], ah[3], uA + ao);
                    #pragma unroll
                    for (int np = 0; np < 2; np++)
                        #pragma unroll
                        for (int half = 0; half < 2; half++)
                            mma_f16(acc[mt][np * 2 + half], ah,
                                    bh[np][half * 2], bh[np][half * 2 + 1]);
                }
            }
            if (producer) {
                if (jnext < NOC * 8) {
                    issue_Aw(wbuf, lane, woff, warp_m, jnext);
                    jnext++;
                }
                CP_COMMIT();
            }
        }

        // ---- epilogue: cropped image write + bias ----
        const int oc0 = ob * 128;
        #pragma unroll
        for (int mt = 0; mt < 2; mt++) {
            const int mBase = warp_m * 32 + mt * 16 + (lane >> 2);
            #pragma unroll
            for (int oct = 0; oct < 4; oct++) {
                const int l = warp_n * 32 + oct * 8 + 2 * (lane & 3);
                const float* d = acc[mt][oct];
                const int hh  = hw * 8 + (l >> 3);
                const int wwp = ww * 8 + (l & 7);
                #pragma unroll
                for (int rr = 0; rr < 2; rr++) {
                    const int oc = oc0 + mBase + rr * 8;
                    const float bs = bias[oc];
                    if (hh < HH) {
                        if (wwp < WW)
                            Out[((size_t)(bo2 * 256 + oc) * HH + hh) * WW + wwp]
                                = d[rr * 2 + 0] + bs;
                        if (wwp + 1 < WW)
                            Out[((size_t)(bo2 * 256 + oc) * HH + hh) * WW + wwp + 1]
                                = d[rr * 2 + 1] + bs;
                    }
                }
            }
        }
    }
}

// ---------------------------------------------------------------------------
// fp16 MMA attention (R16 design, unchanged).
// ---------------------------------------------------------------------------
#define SLAB 4608                 // 32 rows * 144B
#define WHSZ (3 * SLAB)           // Q K V
#define O_OFF (2 * WHSZ)          // 27648
#define O_PITCH 144
#define O_WH (32 * O_PITCH)       // 4608
#define ATT_SMEM (O_OFF + 2 * O_WH)   // 36864

__global__ __launch_bounds__(128)
void attn_mma()
{
    extern __shared__ char smem[];
    const uint32_t sbase = smem_u32(smem);
    const int tid  = threadIdx.x;
    const int wid  = tid >> 5;
    const int lane = tid & 31;

    const __half* srcs[3] = {g_Q, g_K, g_V};
    #pragma unroll
    for (int sl = 0; sl < 2; sl++) {
        const size_t gbase = (size_t)(blockIdx.x * 2 + sl) * 2048;
        #pragma unroll
        for (int a = 0; a < 3; a++) {
            const __half* src = srcs[a] + gbase;
            const uint32_t dstb = sbase + (uint32_t)(sl * WHSZ + a * SLAB);
            #pragma unroll
            for (int i = 0; i < 2; i++) {
                const int idx = i * 128 + tid;           // 0..255, 16B each
                cpa16(dstb + (uint32_t)((idx >> 3) * 144 + (idx & 7) * 16),
                      src + idx * 8);
            }
        }
    }
    CP_COMMIT();
    CP_WAIT(0);
    __syncthreads();

    const uint32_t sb = sbase + (wid >> 1) * WHSZ;
    const uint32_t uQ = sb, uK = sb + SLAB, uV = sb + 2 * SLAB;
    const int whalf = wid & 1;

    const int g = lane >> 2;
    const int t = lane & 3;

    char* obase = smem + O_OFF + (wid >> 1) * O_WH;

    const uint32_t qRow = (uint32_t)((lane & 7) + ((lane >> 4) & 1) * 8);
    const uint32_t qCol = (uint32_t)(((lane >> 3) & 1) * 16);
    const uint32_t kRow = (uint32_t)((lane & 7) + ((lane >> 3) & 1) * 8);
    const uint32_t kCol = (uint32_t)((lane >> 4) * 16);
    const uint32_t vRow = (uint32_t)((lane & 7) + ((lane >> 4) & 1) * 8);
    const uint32_t vCol = (uint32_t)(((lane >> 3) & 1) * 16);

    #pragma unroll
    for (int mt = 0; mt < 2; mt++) {
        const int ltile = whalf * 2 + mt;

        float s[8][4];
        #pragma unroll
        for (int j = 0; j < 8; j++)
            #pragma unroll
            for (int k = 0; k < 4; k++) s[j][k] = 0.f;

        #pragma unroll
        for (int kt = 0; kt < 2; kt++) {
            uint32_t ah[4];
            const uint32_t ao = (qRow + kt * 16) * 144 + qCol + (uint32_t)(ltile * 32);
            LDSM_X4_T(ah[0], ah[1], ah[2], ah[3], uQ + ao);
            #pragma unroll
            for (int nt = 0; nt < 4; nt++) {
                uint32_t bh[4];
                const uint32_t bo = (kRow + kt * 16) * 144 + kCol + (uint32_t)(nt * 32);
                LDSM_X4_T(bh[0], bh[1], bh[2], bh[3], uK + bo);
                #pragma unroll
                for (int half = 0; half < 2; half++)
                    mma_f16(s[nt * 2 + half], ah, bh[half * 2], bh[half * 2 + 1]);
            }
        }

        float mx0 = -1e30f, mx1 = -1e30f;
        #pragma unroll
        for (int j = 0; j < 8; j++) {
            mx0 = fmaxf(mx0, fmaxf(s[j][0], s[j][1]));
            mx1 = fmaxf(mx1, fmaxf(s[j][2], s[j][3]));
        }
        mx0 = fmaxf(mx0, __shfl_xor_sync(0xffffffffu, mx0, 1));
        mx0 = fmaxf(mx0, __shfl_xor_sync(0xffffffffu, mx0, 2));
        mx1 = fmaxf(mx1, __shfl_xor_sync(0xffffffffu, mx1, 1));
        mx1 = fmaxf(mx1, __shfl_xor_sync(0xffffffffu, mx1, 2));

        float sum0 = 0.f, sum1 = 0.f;
        uint32_t ph01[8], ph23[8];
        #pragma unroll
        for (int j = 0; j < 8; j++) {
            const float e0 = __expf(s[j][0] - mx0);
            const float e1 = __expf(s[j][1] - mx0);
            const float e2 = __expf(s[j][2] - mx1);
            const float e3 = __expf(s[j][3] - mx1);
            sum0 += e0 + e1;
            sum1 += e2 + e3;
            ph01[j] = pack_half(e0, e1);
            ph23[j] = pack_half(e2, e3);
        }
        sum0 += __shfl_xor_sync(0xffffffffu, sum0, 1);
        sum0 += __shfl_xor_sync(0xffffffffu, sum0, 2);
        sum1 += __shfl_xor_sync(0xffffffffu, sum1, 1);
        sum1 += __shfl_xor_sync(0xffffffffu, sum1, 2);
        const float inv0 = 1.f / sum0;
        const float inv1 = 1.f / sum1;

        float o[4][4];
        #pragma unroll
        for (int j = 0; j < 4; j++)
            #pragma unroll
            for (int k = 0; k < 4; k++) o[j][k] = 0.f;

        #pragma unroll
        for (int kt = 0; kt < 4; kt++) {
            uint32_t ap[4];
            ap[0] = ph01[2 * kt];     ap[1] = ph23[2 * kt];
            ap[2] = ph01[2 * kt + 1]; ap[3] = ph23[2 * kt + 1];
            #pragma unroll
            for (int dt2 = 0; dt2 < 2; dt2++) {
                uint32_t bh[4];
                const uint32_t bo = (vRow + dt2 * 16) * 144 + vCol + (uint32_t)(kt * 32);
                LDSM_X4(bh[0], bh[1], bh[2], bh[3], uV + bo);
                #pragma unroll
                for (int half = 0; half < 2; half++)
                    mma_f16(o[dt2 * 2 + half], ap, bh[half * 2], bh[half * 2 + 1]);
            }
        }

        const int l0 = ltile * 16 + g;
        const int l1 = l0 + 8;
        #pragma unroll
        for (int dt = 0; dt < 4; dt++) {
            const int d0 = dt * 8 + 2 * t;
            *(__half*)(obase + d0 * O_PITCH + l0 * 2)
                = __float2half_rn(o[dt][0] * inv0);
            *(__half*)(obase + (d0 + 1) * O_PITCH + l0 * 2)
                = __float2half_rn(o[dt][1] * inv0);
            *(__half*)(obase + d0 * O_PITCH + l1 * 2)
                = __float2half_rn(o[dt][2] * inv1);
            *(__half*)(obase + (d0 + 1) * O_PITCH + l1 * 2)
                = __float2half_rn(o[dt][3] * inv1);
        }
    }

    __syncthreads();
    const size_t og = (size_t)blockIdx.x * 4096;
    #pragma unroll
    for (int i = 0; i < 4; i++) {
        const int u = i * 128 + tid;          // 0..511 uint4
        const int whs = u >> 8;
        const int rm  = u & 255;
        const int d = rm >> 3, j = rm & 7;
        const uint4 v = *reinterpret_cast<const uint4*>(
            smem + O_OFF + whs * O_WH + d * O_PITCH + j * 16);
        *reinterpret_cast<uint4*>(g_O + og + whs * 2048 + d * 64 + j * 8) = v;
    }
}

// ---------------------------------------------------------------------------
extern "C" void kernel_launch(void* const* d_in, const int* in_sizes, int n_in,
                              void* d_out, int out_size)
{
    const float* x_q    = (const float*)d_in[0];
    const float* x_kv   = (const float*)d_in[1];
    const float* w_q    = (const float*)d_in[2];
    const float* w_kv   = (const float*)d_in[3];
    const float* w_proj = (const float*)d_in[4];
    const float* b_proj = (const float*)d_in[5];
    float* out = (float*)d_out;

    cudaFuncSetAttribute(attn_mma, cudaFuncAttributeMaxDynamicSharedMemorySize, ATT_SMEM);
    cudaFuncSetAttribute(proj_qkv, cudaFuncAttributeMaxDynamicSharedMemorySize, P_SMEM);
    cudaFuncSetAttribute(proj_out, cudaFuncAttributeMaxDynamicSharedMemorySize, P_SMEM);

    prep_w<<<1024, 256>>>(w_q, w_kv, w_proj);

    proj_qkv<<<8192, 256, P_SMEM>>>(x_q, x_kv);
    attn_mma<<<16384, 128, ATT_SMEM>>>();
    proj_out<<<4096, 256, P_SMEM>>>(b_proj, out);
}